// round 2
// baseline (speedup 1.0000x reference)
#include <cuda_runtime.h>
#include <math.h>

#define TLEN 32768
#define NF   65536
#define TWO_PI 6.283185307179586476925f

// 128 complex signals x 65536 points = 64 MB scratch
__device__ float2 g_work[128 * 65536];
// filter spectrum in the same (digit-transposed) layout
__device__ float2 g_filt[65536];

__device__ __forceinline__ float2 cmul(float2 a, float2 b) {
    return make_float2(fmaf(a.x, b.x, -(a.y * b.y)), fmaf(a.x, b.y, a.y * b.x));
}

template<int SIGN>
__device__ __forceinline__ void fft4(float2& a0, float2& a1, float2& a2, float2& a3) {
    float2 s0 = make_float2(a0.x + a2.x, a0.y + a2.y);
    float2 d0 = make_float2(a0.x - a2.x, a0.y - a2.y);
    float2 s1 = make_float2(a1.x + a3.x, a1.y + a3.y);
    float2 d1 = make_float2(a1.x - a3.x, a1.y - a3.y);
    // w = e^{SIGN*i*pi/2}: w*d1
    float2 wd1 = (SIGN < 0) ? make_float2(d1.y, -d1.x) : make_float2(-d1.y, d1.x);
    a0 = make_float2(s0.x + s1.x, s0.y + s1.y);
    a2 = make_float2(s0.x - s1.x, s0.y - s1.y);
    a1 = make_float2(d0.x + wd1.x, d0.y + wd1.y);
    a3 = make_float2(d0.x - wd1.x, d0.y - wd1.y);
}

template<int SIGN>
__device__ __forceinline__ float2 w16f(int m) {
    const float C[10] = {1.f, 0.92387953251128675613f, 0.70710678118654752440f,
                         0.38268343236508977173f, 0.f, -0.38268343236508977173f,
                         -0.70710678118654752440f, -0.92387953251128675613f,
                         -1.f, -0.92387953251128675613f};
    const float S[10] = {0.f, 0.38268343236508977173f, 0.70710678118654752440f,
                         0.92387953251128675613f, 1.f, 0.92387953251128675613f,
                         0.70710678118654752440f, 0.38268343236508977173f,
                         0.f, -0.38268343236508977173f};
    return make_float2(C[m], (SIGN < 0) ? -S[m] : S[m]);
}

// 16-point DFT, natural-order in/out: X[k] = sum_n v[n] e^{SIGN*2pi i nk/16}
template<int SIGN>
__device__ __forceinline__ void fft16(float2 v[16]) {
    #pragma unroll
    for (int b = 0; b < 4; b++) fft4<SIGN>(v[b], v[4 + b], v[8 + b], v[12 + b]);
    // now y_b[p] sits at v[4p+b]; twiddle by w16^{b*p}
    #pragma unroll
    for (int p = 1; p < 4; p++) {
        #pragma unroll
        for (int b = 1; b < 4; b++)
            v[4 * p + b] = cmul(v[4 * p + b], w16f<SIGN>(b * p));
    }
    #pragma unroll
    for (int p = 0; p < 4; p++) fft4<SIGN>(v[4 * p + 0], v[4 * p + 1], v[4 * p + 2], v[4 * p + 3]);
    // X[4q+p] sits at v[4p+q] -> permute to natural order
    float2 o[16];
    #pragma unroll
    for (int q = 0; q < 4; q++)
        #pragma unroll
        for (int p = 0; p < 4; p++) o[4 * q + p] = v[4 * p + q];
    #pragma unroll
    for (int i = 0; i < 16; i++) v[i] = o[i];
}

// 256-point DFT across 16 lanes (lane l holds v[j]=s[16j+l] on entry;
// on exit lane l holds v[k2]=X[16*k2+l]). Exchange via shared row g.
template<int SIGN>
__device__ __forceinline__ void fft256_core(float2 v[16], int l, int g,
                                            float* shr, float* shi) {
    fft16<SIGN>(v);
    float sv, cv;
    sincosf(((SIGN < 0) ? -TWO_PI : TWO_PI) * (float)l / 256.0f, &sv, &cv);
    float2 w = make_float2(cv, sv);
    float2 t = make_float2(1.f, 0.f);
    #pragma unroll
    for (int k1 = 0; k1 < 16; k1++) { v[k1] = cmul(v[k1], t); t = cmul(t, w); }
    __syncthreads();
    #pragma unroll
    for (int k1 = 0; k1 < 16; k1++) {
        shr[g * 257 + k1 * 16 + l] = v[k1].x;
        shi[g * 257 + k1 * 16 + l] = v[k1].y;
    }
    __syncthreads();
    #pragma unroll
    for (int n2 = 0; n2 < 16; n2++) {
        v[n2] = make_float2(shr[g * 257 + l * 16 + n2], shi[g * 257 + l * 16 + n2]);
    }
    fft16<SIGN>(v);
}

// ---------------- K1: forward column FFT + omega_N^{c k} twiddle ----------------
__global__ void __launch_bounds__(256) k_fwd_col(const float* __restrict__ x) {
    __shared__ float shr[16 * 257];
    __shared__ float shi[16 * 257];
    int tid = threadIdx.x;
    int l = tid >> 4, g = tid & 15;
    int p = blockIdx.x >> 4, ct = blockIdx.x & 15;
    int c = ct * 16 + g;
    const float* xr = x + (size_t)(2 * p) * TLEN;
    const float* xi = x + (size_t)(2 * p + 1) * TLEN;
    float2 v[16];
    #pragma unroll
    for (int j = 0; j < 16; j++) {
        if (j < 8) {  // rows >=128 are zero padding
            int n = (16 * j + l) * 256 + c;
            v[j] = make_float2(xr[n], xi[n]);
        } else v[j] = make_float2(0.f, 0.f);
    }
    fft256_core<-1>(v, l, g, shr, shi);
    // twiddle exp(-2pi i * c * k / 65536), k = 16*k2 + l
    float sb, cb; sincosf(-TWO_PI * (float)(c * l) / 65536.0f, &sb, &cb);
    float ss, cs; sincosf(-TWO_PI * (float)(16 * c) / 65536.0f, &ss, &cs);
    float2 tw = make_float2(cb, sb), wst = make_float2(cs, ss);
    float2* dst = g_work + (size_t)p * NF;
    #pragma unroll
    for (int k2 = 0; k2 < 16; k2++) {
        dst[(16 * k2 + l) * 256 + c] = cmul(v[k2], tw);
        tw = cmul(tw, wst);
    }
}

// ---------------- K0a: filter column FFT + twiddle ----------------
__global__ void __launch_bounds__(256) k_filt_col(const float* __restrict__ f) {
    __shared__ float shr[16 * 257];
    __shared__ float shi[16 * 257];
    int tid = threadIdx.x;
    int l = tid >> 4, g = tid & 15;
    int c = blockIdx.x * 16 + g;
    float2 v[16];
    #pragma unroll
    for (int j = 0; j < 16; j++) {
        if (j < 8) {
            int n = (16 * j + l) * 256 + c;
            v[j] = make_float2(f[n], 0.f);
        } else v[j] = make_float2(0.f, 0.f);
    }
    fft256_core<-1>(v, l, g, shr, shi);
    float sb, cb; sincosf(-TWO_PI * (float)(c * l) / 65536.0f, &sb, &cb);
    float ss, cs; sincosf(-TWO_PI * (float)(16 * c) / 65536.0f, &ss, &cs);
    float2 tw = make_float2(cb, sb), wst = make_float2(cs, ss);
    #pragma unroll
    for (int k2 = 0; k2 < 16; k2++) {
        g_filt[(16 * k2 + l) * 256 + c] = cmul(v[k2], tw);
        tw = cmul(tw, wst);
    }
}

// ---------------- K0b: filter row FFT (in place) ----------------
__global__ void __launch_bounds__(256) k_filt_row() {
    __shared__ float shr[16 * 257];
    __shared__ float shi[16 * 257];
    int tid = threadIdx.x;
    int l = tid >> 4, g = tid & 15;
    int k1base = blockIdx.x * 16;
    float2* base = g_filt + k1base * 256;
    #pragma unroll
    for (int it = 0; it < 16; it++) {
        int idx = tid + 256 * it; int row = idx >> 8; int colp = idx & 255;
        float2 z = base[idx];
        shr[row * 257 + colp] = z.x; shi[row * 257 + colp] = z.y;
    }
    __syncthreads();
    float2 v[16];
    #pragma unroll
    for (int j = 0; j < 16; j++)
        v[j] = make_float2(shr[g * 257 + 16 * j + l], shi[g * 257 + 16 * j + l]);
    fft256_core<-1>(v, l, g, shr, shi);
    __syncthreads();
    #pragma unroll
    for (int k2 = 0; k2 < 16; k2++) {
        shr[g * 257 + 16 * k2 + l] = v[k2].x;
        shi[g * 257 + 16 * k2 + l] = v[k2].y;
    }
    __syncthreads();
    #pragma unroll
    for (int it = 0; it < 16; it++) {
        int idx = tid + 256 * it; int row = idx >> 8; int colp = idx & 255;
        base[idx] = make_float2(shr[row * 257 + colp], shi[row * 257 + colp]);
    }
}

// ---- K2: row FFT -> multiply Wf -> row IFFT -> conj twiddle (fused) ----
__global__ void __launch_bounds__(256) k_row() {
    __shared__ float shr[16 * 257];
    __shared__ float shi[16 * 257];
    int tid = threadIdx.x;
    int l = tid >> 4, g = tid & 15;
    int p = blockIdx.x >> 4, rt = blockIdx.x & 15;
    int k1base = rt * 16;
    float2* base = g_work + (size_t)p * NF + k1base * 256;
    const float2* wf = g_filt + k1base * 256;
    #pragma unroll
    for (int it = 0; it < 16; it++) {
        int idx = tid + 256 * it; int row = idx >> 8; int colp = idx & 255;
        float2 z = base[idx];
        shr[row * 257 + colp] = z.x; shi[row * 257 + colp] = z.y;
    }
    __syncthreads();
    float2 v[16];
    #pragma unroll
    for (int j = 0; j < 16; j++)
        v[j] = make_float2(shr[g * 257 + 16 * j + l], shi[g * 257 + 16 * j + l]);
    fft256_core<-1>(v, l, g, shr, shi);
    __syncthreads();
    #pragma unroll
    for (int k2 = 0; k2 < 16; k2++) {
        shr[g * 257 + 16 * k2 + l] = v[k2].x;
        shi[g * 257 + 16 * k2 + l] = v[k2].y;
    }
    __syncthreads();
    // pointwise multiply by filter spectrum (same permuted layout -> memory order)
    #pragma unroll
    for (int it = 0; it < 16; it++) {
        int idx = tid + 256 * it; int row = idx >> 8; int colp = idx & 255;
        float2 a = make_float2(shr[row * 257 + colp], shi[row * 257 + colp]);
        float2 z = cmul(a, wf[idx]);
        shr[row * 257 + colp] = z.x; shi[row * 257 + colp] = z.y;
    }
    __syncthreads();
    #pragma unroll
    for (int j = 0; j < 16; j++)
        v[j] = make_float2(shr[g * 257 + 16 * j + l], shi[g * 257 + 16 * j + l]);
    fft256_core<1>(v, l, g, shr, shi);
    // conj twiddle exp(+2pi i * n2 * k1 / 65536), n2 = 16*k2 + l, k1 = row
    // (applied ONCE here; k_inv_col must NOT reapply it)
    int k1 = k1base + g;
    float sb, cb; sincosf(TWO_PI * (float)(k1 * l) / 65536.0f, &sb, &cb);
    float ss, cs; sincosf(TWO_PI * (float)(16 * k1) / 65536.0f, &ss, &cs);
    float2 tw = make_float2(cb, sb), wst = make_float2(cs, ss);
    __syncthreads();
    #pragma unroll
    for (int k2 = 0; k2 < 16; k2++) {
        float2 r = cmul(v[k2], tw); tw = cmul(tw, wst);
        shr[g * 257 + 16 * k2 + l] = r.x;
        shi[g * 257 + 16 * k2 + l] = r.y;
    }
    __syncthreads();
    #pragma unroll
    for (int it = 0; it < 16; it++) {
        int idx = tid + 256 * it; int row = idx >> 8; int colp = idx & 255;
        base[idx] = make_float2(shr[row * 257 + colp], shi[row * 257 + colp]);
    }
}

// ---------------- K3: inverse column FFT + scale + write output ----------------
// NOTE: inter-stage twiddle was already applied in k_row; plain IFFT here.
__global__ void __launch_bounds__(256) k_inv_col(float* __restrict__ y) {
    __shared__ float shr[16 * 257];
    __shared__ float shi[16 * 257];
    int tid = threadIdx.x;
    int l = tid >> 4, g = tid & 15;
    int p = blockIdx.x >> 4, ct = blockIdx.x & 15;
    int c = ct * 16 + g;
    const float2* src = g_work + (size_t)p * NF;
    float2 v[16];
    #pragma unroll
    for (int j = 0; j < 16; j++) {
        v[j] = src[(16 * j + l) * 256 + c];
    }
    fft256_core<1>(v, l, g, shr, shi);
    const float inv = 1.0f / 65536.0f;
    float* yr = y + (size_t)(2 * p) * TLEN;
    float* yi = y + (size_t)(2 * p + 1) * TLEN;
    #pragma unroll
    for (int k2 = 0; k2 < 8; k2++) {  // only rows n1 < 128 (n < T)
        int n = (16 * k2 + l) * 256 + c;
        yr[n] = v[k2].x * inv;
        yi[n] = v[k2].y * inv;
    }
}

extern "C" void kernel_launch(void* const* d_in, const int* in_sizes, int n_in,
                              void* d_out, int out_size) {
    const float* x = (const float*)d_in[0];
    const float* f = (const float*)d_in[1];
    float* y = (float*)d_out;

    k_filt_col<<<16, 256>>>(f);     // filter: column FFT + twiddle
    k_filt_row<<<16, 256>>>();      // filter: row FFT -> Wf spectrum
    k_fwd_col<<<2048, 256>>>(x);    // signals: column FFT + twiddle (packed pairs)
    k_row<<<2048, 256>>>();         // row FFT, *Wf, row IFFT, conj twiddle (fused)
    k_inv_col<<<2048, 256>>>(y);    // column IFFT, scale, write y
}

// round 3
// speedup vs baseline: 1.1239x; 1.1239x over previous
#include <cuda_runtime.h>
#include <math.h>

#define TLEN 32768
#define NF   65536
#define TWO_PI 6.283185307179586476925f

// 128 complex signals x 65536 points = 64 MB scratch
__device__ float2 g_work[128 * 65536];
// filter spectrum; after k_filt_row it is stored in the K2 register-matched
// layout: g_filt[rt*4096 + k2*256 + (l*16+g)] = Wf[16*rt+g][16*k2+l]
__device__ float2 g_filt[65536];

__device__ __forceinline__ float2 cmul(float2 a, float2 b) {
    return make_float2(fmaf(a.x, b.x, -(a.y * b.y)), fmaf(a.x, b.y, a.y * b.x));
}

template<int SIGN>
__device__ __forceinline__ void fft4(float2& a0, float2& a1, float2& a2, float2& a3) {
    float2 s0 = make_float2(a0.x + a2.x, a0.y + a2.y);
    float2 d0 = make_float2(a0.x - a2.x, a0.y - a2.y);
    float2 s1 = make_float2(a1.x + a3.x, a1.y + a3.y);
    float2 d1 = make_float2(a1.x - a3.x, a1.y - a3.y);
    float2 wd1 = (SIGN < 0) ? make_float2(d1.y, -d1.x) : make_float2(-d1.y, d1.x);
    a0 = make_float2(s0.x + s1.x, s0.y + s1.y);
    a2 = make_float2(s0.x - s1.x, s0.y - s1.y);
    a1 = make_float2(d0.x + wd1.x, d0.y + wd1.y);
    a3 = make_float2(d0.x - wd1.x, d0.y - wd1.y);
}

template<int SIGN>
__device__ __forceinline__ float2 w16f(int m) {
    const float C[10] = {1.f, 0.92387953251128675613f, 0.70710678118654752440f,
                         0.38268343236508977173f, 0.f, -0.38268343236508977173f,
                         -0.70710678118654752440f, -0.92387953251128675613f,
                         -1.f, -0.92387953251128675613f};
    const float S[10] = {0.f, 0.38268343236508977173f, 0.70710678118654752440f,
                         0.92387953251128675613f, 1.f, 0.92387953251128675613f,
                         0.70710678118654752440f, 0.38268343236508977173f,
                         0.f, -0.38268343236508977173f};
    return make_float2(C[m], (SIGN < 0) ? -S[m] : S[m]);
}

// 16-point DFT, natural-order in/out
template<int SIGN>
__device__ __forceinline__ void fft16(float2 v[16]) {
    #pragma unroll
    for (int b = 0; b < 4; b++) fft4<SIGN>(v[b], v[4 + b], v[8 + b], v[12 + b]);
    #pragma unroll
    for (int p = 1; p < 4; p++) {
        #pragma unroll
        for (int b = 1; b < 4; b++)
            v[4 * p + b] = cmul(v[4 * p + b], w16f<SIGN>(b * p));
    }
    #pragma unroll
    for (int p = 0; p < 4; p++) fft4<SIGN>(v[4 * p + 0], v[4 * p + 1], v[4 * p + 2], v[4 * p + 3]);
    float2 o[16];
    #pragma unroll
    for (int q = 0; q < 4; q++)
        #pragma unroll
        for (int p = 0; p < 4; p++) o[4 * q + p] = v[4 * p + q];
    #pragma unroll
    for (int i = 0; i < 16; i++) v[i] = o[i];
}

// 256-point DFT across 16 lanes (lane l holds v[j]=s[16j+l] on entry;
// on exit lane l holds v[k2]=X[16*k2+l]). Exchange via shared row g.
template<int SIGN>
__device__ __forceinline__ void fft256_core(float2 v[16], int l, int g,
                                            float* shr, float* shi) {
    fft16<SIGN>(v);
    float sv, cv;
    sincosf(((SIGN < 0) ? -TWO_PI : TWO_PI) * (float)l / 256.0f, &sv, &cv);
    float2 w = make_float2(cv, sv);
    float2 t = make_float2(1.f, 0.f);
    #pragma unroll
    for (int k1 = 0; k1 < 16; k1++) { v[k1] = cmul(v[k1], t); t = cmul(t, w); }
    __syncthreads();
    #pragma unroll
    for (int k1 = 0; k1 < 16; k1++) {
        shr[g * 257 + k1 * 16 + l] = v[k1].x;
        shi[g * 257 + k1 * 16 + l] = v[k1].y;
    }
    __syncthreads();
    #pragma unroll
    for (int n2 = 0; n2 < 16; n2++) {
        v[n2] = make_float2(shr[g * 257 + l * 16 + n2], shi[g * 257 + l * 16 + n2]);
    }
    fft16<SIGN>(v);
}

// ---------------- K1: forward column FFT + omega_N^{c k} twiddle ----------------
__global__ void __launch_bounds__(256) k_fwd_col(const float* __restrict__ x) {
    __shared__ float shr[16 * 257];
    __shared__ float shi[16 * 257];
    int tid = threadIdx.x;
    int l = tid >> 4, g = tid & 15;
    int p = blockIdx.x >> 4, ct = blockIdx.x & 15;
    int c = ct * 16 + g;
    const float* xr = x + (size_t)(2 * p) * TLEN;
    const float* xi = x + (size_t)(2 * p + 1) * TLEN;
    float2 v[16];
    #pragma unroll
    for (int j = 0; j < 16; j++) {
        if (j < 8) {  // rows >=128 are zero padding
            int n = (16 * j + l) * 256 + c;
            v[j] = make_float2(xr[n], xi[n]);
        } else v[j] = make_float2(0.f, 0.f);
    }
    fft256_core<-1>(v, l, g, shr, shi);
    // twiddle exp(-2pi i * c * k / 65536), k = 16*k2 + l
    float sb, cb; sincosf(-TWO_PI * (float)(c * l) / 65536.0f, &sb, &cb);
    float ss, cs; sincosf(-TWO_PI * (float)(16 * c) / 65536.0f, &ss, &cs);
    float2 tw = make_float2(cb, sb), wst = make_float2(cs, ss);
    float2* dst = g_work + (size_t)p * NF;
    #pragma unroll
    for (int k2 = 0; k2 < 16; k2++) {
        dst[(16 * k2 + l) * 256 + c] = cmul(v[k2], tw);
        tw = cmul(tw, wst);
    }
}

// ---------------- K0a: filter column FFT + twiddle (natural layout out) --------
__global__ void __launch_bounds__(256) k_filt_col(const float* __restrict__ f) {
    __shared__ float shr[16 * 257];
    __shared__ float shi[16 * 257];
    int tid = threadIdx.x;
    int l = tid >> 4, g = tid & 15;
    int c = blockIdx.x * 16 + g;
    float2 v[16];
    #pragma unroll
    for (int j = 0; j < 16; j++) {
        if (j < 8) {
            int n = (16 * j + l) * 256 + c;
            v[j] = make_float2(f[n], 0.f);
        } else v[j] = make_float2(0.f, 0.f);
    }
    fft256_core<-1>(v, l, g, shr, shi);
    float sb, cb; sincosf(-TWO_PI * (float)(c * l) / 65536.0f, &sb, &cb);
    float ss, cs; sincosf(-TWO_PI * (float)(16 * c) / 65536.0f, &ss, &cs);
    float2 tw = make_float2(cb, sb), wst = make_float2(cs, ss);
    #pragma unroll
    for (int k2 = 0; k2 < 16; k2++) {
        g_filt[(16 * k2 + l) * 256 + c] = cmul(v[k2], tw);
        tw = cmul(tw, wst);
    }
}

// ---- K0b: filter row FFT; writes K2 register-matched layout (in place) ----
__global__ void __launch_bounds__(256) k_filt_row() {
    __shared__ float shr[16 * 257];
    __shared__ float shi[16 * 257];
    int tid = threadIdx.x;
    int l = tid >> 4, g = tid & 15;
    int k1base = blockIdx.x * 16;
    float2* base = g_filt + k1base * 256;
    #pragma unroll
    for (int it = 0; it < 16; it++) {
        int idx = tid + 256 * it; int row = idx >> 8; int colp = idx & 255;
        float2 z = base[idx];
        shr[row * 257 + colp] = z.x; shi[row * 257 + colp] = z.y;
    }
    __syncthreads();
    float2 v[16];
    #pragma unroll
    for (int j = 0; j < 16; j++)
        v[j] = make_float2(shr[g * 257 + 16 * j + l], shi[g * 257 + 16 * j + l]);
    fft256_core<-1>(v, l, g, shr, shi);
    // thread (l,g) holds v[k2] = Wf[k1base+g][16k2+l]; write register-matched
    // layout so K2's multiply is a coalesced register load.
    #pragma unroll
    for (int k2 = 0; k2 < 16; k2++) {
        base[k2 * 256 + tid] = v[k2];
    }
}

// ---- K2: row FFT -> multiply Wf (registers) -> row IFFT -> conj twiddle ----
__global__ void __launch_bounds__(256) k_row() {
    __shared__ float shr[16 * 257];
    __shared__ float shi[16 * 257];
    int tid = threadIdx.x;
    int l = tid >> 4, g = tid & 15;
    int p = blockIdx.x >> 4, rt = blockIdx.x & 15;
    int k1base = rt * 16;
    float2* base = g_work + (size_t)p * NF + k1base * 256;
    const float2* __restrict__ wf = g_filt + k1base * 256;
    // stage-in (coalesced gmem -> smem -> registers)
    #pragma unroll
    for (int it = 0; it < 16; it++) {
        int idx = tid + 256 * it; int row = idx >> 8; int colp = idx & 255;
        float2 z = base[idx];
        shr[row * 257 + colp] = z.x; shi[row * 257 + colp] = z.y;
    }
    __syncthreads();
    float2 v[16];
    #pragma unroll
    for (int j = 0; j < 16; j++)
        v[j] = make_float2(shr[g * 257 + 16 * j + l], shi[g * 257 + 16 * j + l]);
    fft256_core<-1>(v, l, g, shr, shi);
    // pointwise multiply by filter spectrum, entirely in registers
    // (wf layout matches: wf[k2*256 + tid] = Wf[k1base+g][16k2+l])
    #pragma unroll
    for (int k2 = 0; k2 < 16; k2++)
        v[k2] = cmul(v[k2], wf[k2 * 256 + tid]);
    fft256_core<1>(v, l, g, shr, shi);
    // conj twiddle exp(+2pi i * n2 * k1 / 65536), n2 = 16*k2 + l, k1 = row
    int k1 = k1base + g;
    float sb, cb; sincosf(TWO_PI * (float)(k1 * l) / 65536.0f, &sb, &cb);
    float ss, cs; sincosf(TWO_PI * (float)(16 * k1) / 65536.0f, &ss, &cs);
    float2 tw = make_float2(cb, sb), wst = make_float2(cs, ss);
    __syncthreads();
    #pragma unroll
    for (int k2 = 0; k2 < 16; k2++) {
        float2 r = cmul(v[k2], tw); tw = cmul(tw, wst);
        shr[g * 257 + 16 * k2 + l] = r.x;
        shi[g * 257 + 16 * k2 + l] = r.y;
    }
    __syncthreads();
    #pragma unroll
    for (int it = 0; it < 16; it++) {
        int idx = tid + 256 * it; int row = idx >> 8; int colp = idx & 255;
        base[idx] = make_float2(shr[row * 257 + colp], shi[row * 257 + colp]);
    }
}

// ---------------- K3: inverse column FFT + scale + write output ----------------
__global__ void __launch_bounds__(256) k_inv_col(float* __restrict__ y) {
    __shared__ float shr[16 * 257];
    __shared__ float shi[16 * 257];
    int tid = threadIdx.x;
    int l = tid >> 4, g = tid & 15;
    int p = blockIdx.x >> 4, ct = blockIdx.x & 15;
    int c = ct * 16 + g;
    const float2* src = g_work + (size_t)p * NF;
    float2 v[16];
    #pragma unroll
    for (int j = 0; j < 16; j++) {
        v[j] = src[(16 * j + l) * 256 + c];
    }
    fft256_core<1>(v, l, g, shr, shi);
    const float inv = 1.0f / 65536.0f;
    float* yr = y + (size_t)(2 * p) * TLEN;
    float* yi = y + (size_t)(2 * p + 1) * TLEN;
    #pragma unroll
    for (int k2 = 0; k2 < 8; k2++) {  // only rows n1 < 128 (n < T)
        int n = (16 * k2 + l) * 256 + c;
        yr[n] = v[k2].x * inv;
        yi[n] = v[k2].y * inv;
    }
}

extern "C" void kernel_launch(void* const* d_in, const int* in_sizes, int n_in,
                              void* d_out, int out_size) {
    const float* x = (const float*)d_in[0];
    const float* f = (const float*)d_in[1];
    float* y = (float*)d_out;

    k_filt_col<<<16, 256>>>(f);     // filter: column FFT + twiddle
    k_filt_row<<<16, 256>>>();      // filter: row FFT -> K2-matched layout
    k_fwd_col<<<2048, 256>>>(x);    // signals: column FFT + twiddle (packed pairs)
    k_row<<<2048, 256>>>();         // row FFT, *Wf (regs), row IFFT, conj twiddle
    k_inv_col<<<2048, 256>>>(y);    // column IFFT, scale, write y
}

// round 4
// speedup vs baseline: 1.1816x; 1.0514x over previous
#include <cuda_runtime.h>
#include <math.h>

#define TLEN 32768
#define NF   65536
#define TWO_PI 6.283185307179586476925f

// 128 complex signals x 65536 points = 64 MB scratch
__device__ float2 g_work[128 * 65536];
// filter spectrum; after k_filt_row stored in K2 register-matched layout:
// g_filt[rt*4096 + k2*256 + (l*16+g)] = Wf[16*rt+g][16*k2+l]
__device__ float2 g_filt[65536];

__device__ __forceinline__ float2 cmul(float2 a, float2 b) {
    return make_float2(fmaf(a.x, b.x, -(a.y * b.y)), fmaf(a.x, b.y, a.y * b.x));
}

template<int SIGN>
__device__ __forceinline__ void fft4(float2& a0, float2& a1, float2& a2, float2& a3) {
    float2 s0 = make_float2(a0.x + a2.x, a0.y + a2.y);
    float2 d0 = make_float2(a0.x - a2.x, a0.y - a2.y);
    float2 s1 = make_float2(a1.x + a3.x, a1.y + a3.y);
    float2 d1 = make_float2(a1.x - a3.x, a1.y - a3.y);
    float2 wd1 = (SIGN < 0) ? make_float2(d1.y, -d1.x) : make_float2(-d1.y, d1.x);
    a0 = make_float2(s0.x + s1.x, s0.y + s1.y);
    a2 = make_float2(s0.x - s1.x, s0.y - s1.y);
    a1 = make_float2(d0.x + wd1.x, d0.y + wd1.y);
    a3 = make_float2(d0.x - wd1.x, d0.y - wd1.y);
}

template<int SIGN>
__device__ __forceinline__ float2 w16f(int m) {
    const float C[10] = {1.f, 0.92387953251128675613f, 0.70710678118654752440f,
                         0.38268343236508977173f, 0.f, -0.38268343236508977173f,
                         -0.70710678118654752440f, -0.92387953251128675613f,
                         -1.f, -0.92387953251128675613f};
    const float S[10] = {0.f, 0.38268343236508977173f, 0.70710678118654752440f,
                         0.92387953251128675613f, 1.f, 0.92387953251128675613f,
                         0.70710678118654752440f, 0.38268343236508977173f,
                         0.f, -0.38268343236508977173f};
    return make_float2(C[m], (SIGN < 0) ? -S[m] : S[m]);
}

// 16-point DFT, natural-order in/out
template<int SIGN>
__device__ __forceinline__ void fft16(float2 v[16]) {
    #pragma unroll
    for (int b = 0; b < 4; b++) fft4<SIGN>(v[b], v[4 + b], v[8 + b], v[12 + b]);
    #pragma unroll
    for (int p = 1; p < 4; p++) {
        #pragma unroll
        for (int b = 1; b < 4; b++)
            v[4 * p + b] = cmul(v[4 * p + b], w16f<SIGN>(b * p));
    }
    #pragma unroll
    for (int p = 0; p < 4; p++) fft4<SIGN>(v[4 * p + 0], v[4 * p + 1], v[4 * p + 2], v[4 * p + 3]);
    float2 o[16];
    #pragma unroll
    for (int q = 0; q < 4; q++)
        #pragma unroll
        for (int p = 0; p < 4; p++) o[4 * q + p] = v[4 * p + q];
    #pragma unroll
    for (int i = 0; i < 16; i++) v[i] = o[i];
}

// 256-point DFT across 16 lanes (lane l holds v[j]=s[16j+l] on entry;
// on exit lane l holds v[k2]=X[16*k2+l]). Exchange via shared row g.
template<int SIGN>
__device__ __forceinline__ void fft256_core(float2 v[16], int l, int g,
                                            float2* sh) {
    fft16<SIGN>(v);
    float sv, cv;
    sincosf(((SIGN < 0) ? -TWO_PI : TWO_PI) * (float)l / 256.0f, &sv, &cv);
    float2 w = make_float2(cv, sv);
    float2 t = make_float2(1.f, 0.f);
    #pragma unroll
    for (int k1 = 0; k1 < 16; k1++) { v[k1] = cmul(v[k1], t); t = cmul(t, w); }
    __syncthreads();
    #pragma unroll
    for (int k1 = 0; k1 < 16; k1++)
        sh[g * 257 + k1 * 16 + l] = v[k1];
    __syncthreads();
    #pragma unroll
    for (int n2 = 0; n2 < 16; n2++)
        v[n2] = sh[g * 257 + l * 16 + n2];
    fft16<SIGN>(v);
}

// ---------------- K1: forward column FFT + omega_N^{c k} twiddle ----------------
__global__ void __launch_bounds__(256) k_fwd_col(const float* __restrict__ x) {
    __shared__ float2 sh[16 * 257];
    int tid = threadIdx.x;
    int l = tid >> 4, g = tid & 15;
    int p = blockIdx.x >> 4, ct = blockIdx.x & 15;
    int c = ct * 16 + g;
    const float* xr = x + (size_t)(2 * p) * TLEN;
    const float* xi = x + (size_t)(2 * p + 1) * TLEN;
    float2 v[16];
    #pragma unroll
    for (int j = 0; j < 16; j++) {
        if (j < 8) {  // rows >=128 are zero padding
            int n = (16 * j + l) * 256 + c;
            v[j] = make_float2(xr[n], xi[n]);
        } else v[j] = make_float2(0.f, 0.f);
    }
    fft256_core<-1>(v, l, g, sh);
    // twiddle exp(-2pi i * c * k / 65536), k = 16*k2 + l
    float sb, cb; sincosf(-TWO_PI * (float)(c * l) / 65536.0f, &sb, &cb);
    float ss, cs; sincosf(-TWO_PI * (float)(16 * c) / 65536.0f, &ss, &cs);
    float2 tw = make_float2(cb, sb), wst = make_float2(cs, ss);
    float2* dst = g_work + (size_t)p * NF;
    #pragma unroll
    for (int k2 = 0; k2 < 16; k2++) {
        dst[(16 * k2 + l) * 256 + c] = cmul(v[k2], tw);
        tw = cmul(tw, wst);
    }
}

// ---------------- K0a: filter column FFT + twiddle (natural layout out) --------
__global__ void __launch_bounds__(256) k_filt_col(const float* __restrict__ f) {
    __shared__ float2 sh[16 * 257];
    int tid = threadIdx.x;
    int l = tid >> 4, g = tid & 15;
    int c = blockIdx.x * 16 + g;
    float2 v[16];
    #pragma unroll
    for (int j = 0; j < 16; j++) {
        if (j < 8) {
            int n = (16 * j + l) * 256 + c;
            v[j] = make_float2(f[n], 0.f);
        } else v[j] = make_float2(0.f, 0.f);
    }
    fft256_core<-1>(v, l, g, sh);
    float sb, cb; sincosf(-TWO_PI * (float)(c * l) / 65536.0f, &sb, &cb);
    float ss, cs; sincosf(-TWO_PI * (float)(16 * c) / 65536.0f, &ss, &cs);
    float2 tw = make_float2(cb, sb), wst = make_float2(cs, ss);
    #pragma unroll
    for (int k2 = 0; k2 < 16; k2++) {
        g_filt[(16 * k2 + l) * 256 + c] = cmul(v[k2], tw);
        tw = cmul(tw, wst);
    }
}

// ---- K0b: filter row FFT; writes K2 register-matched layout (in place) ----
__global__ void __launch_bounds__(256) k_filt_row() {
    __shared__ float2 sh[16 * 257];
    int tid = threadIdx.x;
    int l = tid >> 4, g = tid & 15;
    int k1base = blockIdx.x * 16;
    float2* base = g_filt + k1base * 256;
    #pragma unroll
    for (int it = 0; it < 16; it++) {
        int idx = tid + 256 * it; int row = idx >> 8; int colp = idx & 255;
        sh[row * 257 + colp] = base[idx];
    }
    __syncthreads();
    float2 v[16];
    #pragma unroll
    for (int j = 0; j < 16; j++)
        v[j] = sh[g * 257 + 16 * j + l];
    fft256_core<-1>(v, l, g, sh);
    // thread (l,g) holds v[k2] = Wf[k1base+g][16k2+l]; write register-matched
    #pragma unroll
    for (int k2 = 0; k2 < 16; k2++)
        base[k2 * 256 + tid] = v[k2];
}

// ---- K2: row FFT -> multiply Wf (registers) -> row IFFT -> conj twiddle ----
__global__ void __launch_bounds__(256) k_row() {
    __shared__ float2 sh[16 * 257];
    int tid = threadIdx.x;
    int l = tid >> 4, g = tid & 15;
    int p = blockIdx.x >> 4, rt = blockIdx.x & 15;
    int k1base = rt * 16;
    float2* base = g_work + (size_t)p * NF + k1base * 256;
    const float2* __restrict__ wf = g_filt + k1base * 256;
    // stage-in (coalesced gmem -> smem -> registers)
    #pragma unroll
    for (int it = 0; it < 16; it++) {
        int idx = tid + 256 * it; int row = idx >> 8; int colp = idx & 255;
        sh[row * 257 + colp] = base[idx];
    }
    __syncthreads();
    float2 v[16];
    #pragma unroll
    for (int j = 0; j < 16; j++)
        v[j] = sh[g * 257 + 16 * j + l];
    fft256_core<-1>(v, l, g, sh);
    // pointwise multiply by filter spectrum, entirely in registers
    #pragma unroll
    for (int k2 = 0; k2 < 16; k2++)
        v[k2] = cmul(v[k2], wf[k2 * 256 + tid]);
    fft256_core<1>(v, l, g, sh);
    // conj twiddle exp(+2pi i * n2 * k1 / 65536), n2 = 16*k2 + l, k1 = row
    int k1 = k1base + g;
    float sb, cb; sincosf(TWO_PI * (float)(k1 * l) / 65536.0f, &sb, &cb);
    float ss, cs; sincosf(TWO_PI * (float)(16 * k1) / 65536.0f, &ss, &cs);
    float2 tw = make_float2(cb, sb), wst = make_float2(cs, ss);
    __syncthreads();
    #pragma unroll
    for (int k2 = 0; k2 < 16; k2++) {
        float2 r = cmul(v[k2], tw); tw = cmul(tw, wst);
        sh[g * 257 + 16 * k2 + l] = r;
    }
    __syncthreads();
    #pragma unroll
    for (int it = 0; it < 16; it++) {
        int idx = tid + 256 * it; int row = idx >> 8; int colp = idx & 255;
        base[idx] = sh[row * 257 + colp];
    }
}

// ---------------- K3: inverse column FFT + scale + write output ----------------
__global__ void __launch_bounds__(256) k_inv_col(float* __restrict__ y) {
    __shared__ float2 sh[16 * 257];
    int tid = threadIdx.x;
    int l = tid >> 4, g = tid & 15;
    int p = blockIdx.x >> 4, ct = blockIdx.x & 15;
    int c = ct * 16 + g;
    const float2* src = g_work + (size_t)p * NF;
    float2 v[16];
    #pragma unroll
    for (int j = 0; j < 16; j++)
        v[j] = src[(16 * j + l) * 256 + c];
    fft256_core<1>(v, l, g, sh);
    const float inv = 1.0f / 65536.0f;
    float* yr = y + (size_t)(2 * p) * TLEN;
    float* yi = y + (size_t)(2 * p + 1) * TLEN;
    #pragma unroll
    for (int k2 = 0; k2 < 8; k2++) {  // only rows n1 < 128 (n < T)
        int n = (16 * k2 + l) * 256 + c;
        yr[n] = v[k2].x * inv;
        yi[n] = v[k2].y * inv;
    }
}

extern "C" void kernel_launch(void* const* d_in, const int* in_sizes, int n_in,
                              void* d_out, int out_size) {
    const float* x = (const float*)d_in[0];
    const float* f = (const float*)d_in[1];
    float* y = (float*)d_out;

    k_filt_col<<<16, 256>>>(f);     // filter: column FFT + twiddle
    k_filt_row<<<16, 256>>>();      // filter: row FFT -> K2-matched layout
    k_fwd_col<<<2048, 256>>>(x);    // signals: column FFT + twiddle (packed pairs)
    k_row<<<2048, 256>>>();         // row FFT, *Wf (regs), row IFFT, conj twiddle
    k_inv_col<<<2048, 256>>>(y);    // column IFFT, scale, write y
}

// round 5
// speedup vs baseline: 1.3111x; 1.1096x over previous
#include <cuda_runtime.h>
#include <math.h>

#define TLEN 32768
#define NF   65536
#define TWO_PI 6.283185307179586476925f

// 128 complex signals x 65536 points = 64 MB scratch
__device__ float2 g_work[128 * 65536];
// filter spectrum; after k_filt_row stored in K2 register-matched layout:
// g_filt[rt*4096 + k2*256 + (l*16+g)] = Wf[16*rt+g][16*k2+l]
__device__ float2 g_filt[65536];

__device__ __forceinline__ float2 cmul(float2 a, float2 b) {
    return make_float2(fmaf(a.x, b.x, -(a.y * b.y)), fmaf(a.x, b.y, a.y * b.x));
}

// packed f32x2 add/sub (Blackwell): 1 instruction for a complex add/sub
__device__ __forceinline__ float2 f2add(float2 a, float2 b) {
    float2 c;
    asm("{\n\t.reg .b64 ra, rb, rc;\n\t"
        "mov.b64 ra, {%2, %3};\n\t"
        "mov.b64 rb, {%4, %5};\n\t"
        "add.rn.f32x2 rc, ra, rb;\n\t"
        "mov.b64 {%0, %1}, rc;\n\t}"
        : "=f"(c.x), "=f"(c.y)
        : "f"(a.x), "f"(a.y), "f"(b.x), "f"(b.y));
    return c;
}
__device__ __forceinline__ float2 f2sub(float2 a, float2 b) {
    float2 c;
    asm("{\n\t.reg .b64 ra, rb, rc;\n\t"
        "mov.b64 ra, {%2, %3};\n\t"
        "mov.b64 rb, {%4, %5};\n\t"
        "sub.rn.f32x2 rc, ra, rb;\n\t"
        "mov.b64 {%0, %1}, rc;\n\t}"
        : "=f"(c.x), "=f"(c.y)
        : "f"(a.x), "f"(a.y), "f"(b.x), "f"(b.y));
    return c;
}

template<int SIGN>
__device__ __forceinline__ void fft4(float2& a0, float2& a1, float2& a2, float2& a3) {
    float2 s0 = f2add(a0, a2);
    float2 d0 = f2sub(a0, a2);
    float2 s1 = f2add(a1, a3);
    float2 d1 = f2sub(a1, a3);
    float2 wd1 = (SIGN < 0) ? make_float2(d1.y, -d1.x) : make_float2(-d1.y, d1.x);
    a0 = f2add(s0, s1);
    a2 = f2sub(s0, s1);
    a1 = f2add(d0, wd1);
    a3 = f2sub(d0, wd1);
}

template<int SIGN>
__device__ __forceinline__ float2 w16f(int m) {
    const float C[10] = {1.f, 0.92387953251128675613f, 0.70710678118654752440f,
                         0.38268343236508977173f, 0.f, -0.38268343236508977173f,
                         -0.70710678118654752440f, -0.92387953251128675613f,
                         -1.f, -0.92387953251128675613f};
    const float S[10] = {0.f, 0.38268343236508977173f, 0.70710678118654752440f,
                         0.92387953251128675613f, 1.f, 0.92387953251128675613f,
                         0.70710678118654752440f, 0.38268343236508977173f,
                         0.f, -0.38268343236508977173f};
    return make_float2(C[m], (SIGN < 0) ? -S[m] : S[m]);
}

// 16-point DFT, natural-order in/out
template<int SIGN>
__device__ __forceinline__ void fft16(float2 v[16]) {
    #pragma unroll
    for (int b = 0; b < 4; b++) fft4<SIGN>(v[b], v[4 + b], v[8 + b], v[12 + b]);
    #pragma unroll
    for (int p = 1; p < 4; p++) {
        #pragma unroll
        for (int b = 1; b < 4; b++)
            v[4 * p + b] = cmul(v[4 * p + b], w16f<SIGN>(b * p));
    }
    #pragma unroll
    for (int p = 0; p < 4; p++) fft4<SIGN>(v[4 * p + 0], v[4 * p + 1], v[4 * p + 2], v[4 * p + 3]);
    float2 o[16];
    #pragma unroll
    for (int q = 0; q < 4; q++)
        #pragma unroll
        for (int p = 0; p < 4; p++) o[4 * q + p] = v[4 * p + q];
    #pragma unroll
    for (int i = 0; i < 16; i++) v[i] = o[i];
}

// 256-point DFT across 16 lanes (lane l holds v[j]=s[16j+l] on entry;
// on exit lane l holds v[k2]=X[16*k2+l]). Exchange via shared row g.
template<int SIGN>
__device__ __forceinline__ void fft256_core(float2 v[16], int l, int g,
                                            float2* sh) {
    fft16<SIGN>(v);
    float sv, cv;
    __sincosf(((SIGN < 0) ? -TWO_PI : TWO_PI) * (float)l / 256.0f, &sv, &cv);
    float2 w = make_float2(cv, sv);
    float2 t = make_float2(1.f, 0.f);
    #pragma unroll
    for (int k1 = 0; k1 < 16; k1++) { v[k1] = cmul(v[k1], t); t = cmul(t, w); }
    __syncthreads();
    #pragma unroll
    for (int k1 = 0; k1 < 16; k1++)
        sh[g * 257 + k1 * 16 + l] = v[k1];
    __syncthreads();
    #pragma unroll
    for (int n2 = 0; n2 < 16; n2++)
        v[n2] = sh[g * 257 + l * 16 + n2];
    fft16<SIGN>(v);
}

// ---------------- K1: forward column FFT + omega_N^{c k} twiddle ----------------
__global__ void __launch_bounds__(256) k_fwd_col(const float* __restrict__ x) {
    __shared__ float2 sh[16 * 257];
    int tid = threadIdx.x;
    int l = tid >> 4, g = tid & 15;
    int p = blockIdx.x >> 4, ct = blockIdx.x & 15;
    int c = ct * 16 + g;
    const float* xr = x + (size_t)(2 * p) * TLEN;
    const float* xi = x + (size_t)(2 * p + 1) * TLEN;
    float2 v[16];
    #pragma unroll
    for (int j = 0; j < 16; j++) {
        if (j < 8) {  // rows >=128 are zero padding
            int n = (16 * j + l) * 256 + c;
            v[j] = make_float2(xr[n], xi[n]);
        } else v[j] = make_float2(0.f, 0.f);
    }
    fft256_core<-1>(v, l, g, sh);
    // twiddle exp(-2pi i * c * k / 65536), k = 16*k2 + l
    float sb, cb; __sincosf(-TWO_PI * (float)(c * l) / 65536.0f, &sb, &cb);
    float ss, cs; __sincosf(-TWO_PI * (float)(16 * c) / 65536.0f, &ss, &cs);
    float2 tw = make_float2(cb, sb), wst = make_float2(cs, ss);
    float2* dst = g_work + (size_t)p * NF;
    #pragma unroll
    for (int k2 = 0; k2 < 16; k2++) {
        dst[(16 * k2 + l) * 256 + c] = cmul(v[k2], tw);
        tw = cmul(tw, wst);
    }
}

// ---------------- K0a: filter column FFT + twiddle (natural layout out) --------
__global__ void __launch_bounds__(256) k_filt_col(const float* __restrict__ f) {
    __shared__ float2 sh[16 * 257];
    int tid = threadIdx.x;
    int l = tid >> 4, g = tid & 15;
    int c = blockIdx.x * 16 + g;
    float2 v[16];
    #pragma unroll
    for (int j = 0; j < 16; j++) {
        if (j < 8) {
            int n = (16 * j + l) * 256 + c;
            v[j] = make_float2(f[n], 0.f);
        } else v[j] = make_float2(0.f, 0.f);
    }
    fft256_core<-1>(v, l, g, sh);
    float sb, cb; __sincosf(-TWO_PI * (float)(c * l) / 65536.0f, &sb, &cb);
    float ss, cs; __sincosf(-TWO_PI * (float)(16 * c) / 65536.0f, &ss, &cs);
    float2 tw = make_float2(cb, sb), wst = make_float2(cs, ss);
    #pragma unroll
    for (int k2 = 0; k2 < 16; k2++) {
        g_filt[(16 * k2 + l) * 256 + c] = cmul(v[k2], tw);
        tw = cmul(tw, wst);
    }
}

// ---- K0b: filter row FFT; writes K2 register-matched layout (in place) ----
__global__ void __launch_bounds__(256) k_filt_row() {
    __shared__ float2 sh[16 * 257];
    int tid = threadIdx.x;
    int l = tid >> 4, g = tid & 15;
    int k1base = blockIdx.x * 16;
    float2* base = g_filt + k1base * 256;
    #pragma unroll
    for (int it = 0; it < 16; it++) {
        int idx = tid + 256 * it; int row = idx >> 8; int colp = idx & 255;
        sh[row * 257 + colp] = base[idx];
    }
    __syncthreads();
    float2 v[16];
    #pragma unroll
    for (int j = 0; j < 16; j++)
        v[j] = sh[g * 257 + 16 * j + l];
    fft256_core<-1>(v, l, g, sh);
    // thread (l,g) holds v[k2] = Wf[k1base+g][16k2+l]; write register-matched
    #pragma unroll
    for (int k2 = 0; k2 < 16; k2++)
        base[k2 * 256 + tid] = v[k2];
}

// ---- K2: row FFT -> multiply Wf (registers) -> row IFFT -> conj twiddle ----
__global__ void __launch_bounds__(256) k_row() {
    __shared__ float2 sh[16 * 257];
    int tid = threadIdx.x;
    int l = tid >> 4, g = tid & 15;
    int p = blockIdx.x >> 4, rt = blockIdx.x & 15;
    int k1base = rt * 16;
    float2* base = g_work + (size_t)p * NF + k1base * 256;
    const float2* __restrict__ wf = g_filt + k1base * 256;
    // stage-in (coalesced gmem -> smem -> registers)
    #pragma unroll
    for (int it = 0; it < 16; it++) {
        int idx = tid + 256 * it; int row = idx >> 8; int colp = idx & 255;
        sh[row * 257 + colp] = base[idx];
    }
    __syncthreads();
    float2 v[16];
    #pragma unroll
    for (int j = 0; j < 16; j++)
        v[j] = sh[g * 257 + 16 * j + l];
    fft256_core<-1>(v, l, g, sh);
    // pointwise multiply by filter spectrum, entirely in registers
    #pragma unroll
    for (int k2 = 0; k2 < 16; k2++)
        v[k2] = cmul(v[k2], wf[k2 * 256 + tid]);
    fft256_core<1>(v, l, g, sh);
    // conj twiddle exp(+2pi i * n2 * k1 / 65536), n2 = 16*k2 + l, k1 = row
    int k1 = k1base + g;
    float sb, cb; __sincosf(TWO_PI * (float)(k1 * l) / 65536.0f, &sb, &cb);
    float ss, cs; __sincosf(TWO_PI * (float)(16 * k1) / 65536.0f, &ss, &cs);
    float2 tw = make_float2(cb, sb), wst = make_float2(cs, ss);
    __syncthreads();
    #pragma unroll
    for (int k2 = 0; k2 < 16; k2++) {
        float2 r = cmul(v[k2], tw); tw = cmul(tw, wst);
        sh[g * 257 + 16 * k2 + l] = r;
    }
    __syncthreads();
    #pragma unroll
    for (int it = 0; it < 16; it++) {
        int idx = tid + 256 * it; int row = idx >> 8; int colp = idx & 255;
        base[idx] = sh[row * 257 + colp];
    }
}

// ---------------- K3: inverse column FFT + scale + write output ----------------
__global__ void __launch_bounds__(256) k_inv_col(float* __restrict__ y) {
    __shared__ float2 sh[16 * 257];
    int tid = threadIdx.x;
    int l = tid >> 4, g = tid & 15;
    int p = blockIdx.x >> 4, ct = blockIdx.x & 15;
    int c = ct * 16 + g;
    const float2* src = g_work + (size_t)p * NF;
    float2 v[16];
    #pragma unroll
    for (int j = 0; j < 16; j++)
        v[j] = src[(16 * j + l) * 256 + c];
    fft256_core<1>(v, l, g, sh);
    const float inv = 1.0f / 65536.0f;
    float* yr = y + (size_t)(2 * p) * TLEN;
    float* yi = y + (size_t)(2 * p + 1) * TLEN;
    #pragma unroll
    for (int k2 = 0; k2 < 8; k2++) {  // only rows n1 < 128 (n < T)
        int n = (16 * k2 + l) * 256 + c;
        yr[n] = v[k2].x * inv;
        yi[n] = v[k2].y * inv;
    }
}

extern "C" void kernel_launch(void* const* d_in, const int* in_sizes, int n_in,
                              void* d_out, int out_size) {
    const float* x = (const float*)d_in[0];
    const float* f = (const float*)d_in[1];
    float* y = (float*)d_out;

    k_filt_col<<<16, 256>>>(f);     // filter: column FFT + twiddle
    k_filt_row<<<16, 256>>>();      // filter: row FFT -> K2-matched layout
    k_fwd_col<<<2048, 256>>>(x);    // signals: column FFT + twiddle (packed pairs)
    k_row<<<2048, 256>>>();         // row FFT, *Wf (regs), row IFFT, conj twiddle
    k_inv_col<<<2048, 256>>>(y);    // column IFFT, scale, write y
}

// round 6
// speedup vs baseline: 1.3536x; 1.0324x over previous
#include <cuda_runtime.h>
#include <math.h>

#define TLEN 32768
#define NF   65536
#define TWO_PI 6.283185307179586476925f

// 128 complex signals x 65536 points = 64 MB scratch.
// Layout between kernels: g_work[p][k1*4096 + n2]  (k1 = 0..15, n2 = 0..4095)
__device__ float2 g_work[128 * 65536];
// filter spectrum; after k_filt_rowB stored K2-register-matched:
// g_filt[k1*4096 + u2*256 + t]
__device__ float2 g_filt[65536];

__device__ __forceinline__ float2 cmul(float2 a, float2 b) {
    return make_float2(fmaf(a.x, b.x, -(a.y * b.y)), fmaf(a.x, b.y, a.y * b.x));
}

// packed f32x2 add/sub (Blackwell): 1 instruction for a complex add/sub
__device__ __forceinline__ float2 f2add(float2 a, float2 b) {
    float2 c;
    asm("{\n\t.reg .b64 ra, rb, rc;\n\t"
        "mov.b64 ra, {%2, %3};\n\t"
        "mov.b64 rb, {%4, %5};\n\t"
        "add.rn.f32x2 rc, ra, rb;\n\t"
        "mov.b64 {%0, %1}, rc;\n\t}"
        : "=f"(c.x), "=f"(c.y)
        : "f"(a.x), "f"(a.y), "f"(b.x), "f"(b.y));
    return c;
}
__device__ __forceinline__ float2 f2sub(float2 a, float2 b) {
    float2 c;
    asm("{\n\t.reg .b64 ra, rb, rc;\n\t"
        "mov.b64 ra, {%2, %3};\n\t"
        "mov.b64 rb, {%4, %5};\n\t"
        "sub.rn.f32x2 rc, ra, rb;\n\t"
        "mov.b64 {%0, %1}, rc;\n\t}"
        : "=f"(c.x), "=f"(c.y)
        : "f"(a.x), "f"(a.y), "f"(b.x), "f"(b.y));
    return c;
}

template<int SIGN>
__device__ __forceinline__ void fft4(float2& a0, float2& a1, float2& a2, float2& a3) {
    float2 s0 = f2add(a0, a2);
    float2 d0 = f2sub(a0, a2);
    float2 s1 = f2add(a1, a3);
    float2 d1 = f2sub(a1, a3);
    float2 wd1 = (SIGN < 0) ? make_float2(d1.y, -d1.x) : make_float2(-d1.y, d1.x);
    a0 = f2add(s0, s1);
    a2 = f2sub(s0, s1);
    a1 = f2add(d0, wd1);
    a3 = f2sub(d0, wd1);
}

template<int SIGN>
__device__ __forceinline__ float2 w16f(int m) {
    const float C[10] = {1.f, 0.92387953251128675613f, 0.70710678118654752440f,
                         0.38268343236508977173f, 0.f, -0.38268343236508977173f,
                         -0.70710678118654752440f, -0.92387953251128675613f,
                         -1.f, -0.92387953251128675613f};
    const float S[10] = {0.f, 0.38268343236508977173f, 0.70710678118654752440f,
                         0.92387953251128675613f, 1.f, 0.92387953251128675613f,
                         0.70710678118654752440f, 0.38268343236508977173f,
                         0.f, -0.38268343236508977173f};
    return make_float2(C[m], (SIGN < 0) ? -S[m] : S[m]);
}

// 16-point DFT, natural-order in/out: X[k] = sum_n v[n] e^{SIGN*2pi i nk/16}
template<int SIGN>
__device__ __forceinline__ void fft16(float2 v[16]) {
    #pragma unroll
    for (int b = 0; b < 4; b++) fft4<SIGN>(v[b], v[4 + b], v[8 + b], v[12 + b]);
    #pragma unroll
    for (int p = 1; p < 4; p++) {
        #pragma unroll
        for (int b = 1; b < 4; b++)
            v[4 * p + b] = cmul(v[4 * p + b], w16f<SIGN>(b * p));
    }
    #pragma unroll
    for (int p = 0; p < 4; p++) fft4<SIGN>(v[4 * p + 0], v[4 * p + 1], v[4 * p + 2], v[4 * p + 3]);
    float2 o[16];
    #pragma unroll
    for (int q = 0; q < 4; q++)
        #pragma unroll
        for (int p = 0; p < 4; p++) o[4 * q + p] = v[4 * p + q];
    #pragma unroll
    for (int i = 0; i < 16; i++) v[i] = o[i];
}

// 256-point DFT across 16 lanes (lane l holds v[j]=s[16j+l] on entry;
// on exit lane l holds v[k2]=X[16*k2+l]). Exchange via shared row g.
template<int SIGN>
__device__ __forceinline__ void fft256_core(float2 v[16], int l, int g,
                                            float2* sh) {
    fft16<SIGN>(v);
    float sv, cv;
    __sincosf(((SIGN < 0) ? -TWO_PI : TWO_PI) * (float)l / 256.0f, &sv, &cv);
    float2 w = make_float2(cv, sv);
    float2 t = make_float2(1.f, 0.f);
    #pragma unroll
    for (int k1 = 0; k1 < 16; k1++) { v[k1] = cmul(v[k1], t); t = cmul(t, w); }
    __syncthreads();
    #pragma unroll
    for (int k1 = 0; k1 < 16; k1++)
        sh[g * 257 + k1 * 16 + l] = v[k1];
    __syncthreads();
    #pragma unroll
    for (int n2 = 0; n2 < 16; n2++)
        v[n2] = sh[g * 257 + l * 16 + n2];
    fft16<SIGN>(v);
}

// ======== K1: stage A (16-pt column FFT over n1, stride 4096) — no smem ========
// x packed as complex pairs; thread t of block (p, blk) handles n2 = blk*256+t.
__global__ void __launch_bounds__(256) k_colA(const float* __restrict__ x) {
    int t = threadIdx.x;
    int p = blockIdx.x >> 4, blk = blockIdx.x & 15;
    int n2 = blk * 256 + t;
    const float* xr = x + (size_t)(2 * p) * TLEN;
    const float* xi = x + (size_t)(2 * p + 1) * TLEN;
    float2 v[16];
    #pragma unroll
    for (int n1 = 0; n1 < 16; n1++) {
        if (n1 < 8) {  // n >= 32768 is zero padding
            int n = n1 * 4096 + n2;
            v[n1] = make_float2(xr[n], xi[n]);
        } else v[n1] = make_float2(0.f, 0.f);
    }
    fft16<-1>(v);  // over n1 -> v[k1]
    // twiddle e^{-2pi i n2 k1 / 65536}
    float s, c; __sincosf(-TWO_PI * (float)n2 / 65536.0f, &s, &c);
    float2 w = make_float2(c, s), tw = make_float2(1.f, 0.f);
    float2* dst = g_work + (size_t)p * NF;
    #pragma unroll
    for (int k1 = 0; k1 < 16; k1++) {
        dst[k1 * 4096 + n2] = cmul(v[k1], tw);
        tw = cmul(tw, w);
    }
}

// ======== K0a: filter stage A (same as K1, real input, natural layout) ========
__global__ void __launch_bounds__(256) k_filt_colA(const float* __restrict__ f) {
    int t = threadIdx.x;
    int n2 = blockIdx.x * 256 + t;
    float2 v[16];
    #pragma unroll
    for (int n1 = 0; n1 < 16; n1++) {
        if (n1 < 8) v[n1] = make_float2(f[n1 * 4096 + n2], 0.f);
        else v[n1] = make_float2(0.f, 0.f);
    }
    fft16<-1>(v);
    float s, c; __sincosf(-TWO_PI * (float)n2 / 65536.0f, &s, &c);
    float2 w = make_float2(c, s), tw = make_float2(1.f, 0.f);
    #pragma unroll
    for (int k1 = 0; k1 < 16; k1++) {
        g_filt[k1 * 4096 + n2] = cmul(v[k1], tw);
        tw = cmul(tw, w);
    }
}

// ======== K0b: filter row-forward (4096-pt), writes K2-register-matched ========
__global__ void __launch_bounds__(256) k_filt_rowB() {
    __shared__ float2 sh[16 * 257];
    int t = threadIdx.x;
    int l = t >> 4, g = t & 15;
    int k1 = blockIdx.x;
    float2* base = g_filt + k1 * 4096;
    float2 v[16];
    #pragma unroll
    for (int a = 0; a < 16; a++) v[a] = base[a * 256 + t];
    fft16<-1>(v);  // over a -> v[t1] = F[t1][s=t]
    // T1 twiddle e^{-2pi i t * t1 / 4096}
    { float s_, c_; __sincosf(-TWO_PI * (float)t / 4096.0f, &s_, &c_);
      float2 w = make_float2(c_, s_), tw = make_float2(1.f, 0.f);
      #pragma unroll
      for (int t1 = 0; t1 < 16; t1++) { v[t1] = cmul(v[t1], tw); tw = cmul(tw, w); } }
    // transpose: thread (l,g) gets row t1=g, elements s=16j+l
    #pragma unroll
    for (int t1 = 0; t1 < 16; t1++) sh[t1 * 257 + t] = v[t1];
    __syncthreads();
    #pragma unroll
    for (int j = 0; j < 16; j++) v[j] = sh[g * 257 + 16 * j + l];
    fft256_core<-1>(v, l, g, sh);
    // v[u2] = Wf[k1-row][u = 16u2+l] for t1=g; store K2-matched layout
    #pragma unroll
    for (int u2 = 0; u2 < 16; u2++) base[u2 * 256 + t] = v[u2];
}

// ======== K2: per-row 4096-pt FFT -> *Wf -> inverse -> conj inter-twiddle ========
__global__ void __launch_bounds__(256) k_rowB() {
    __shared__ float2 sh[16 * 257];
    int t = threadIdx.x;
    int l = t >> 4, g = t & 15;
    int p = blockIdx.x >> 4, k1 = blockIdx.x & 15;
    float2* base = g_work + (size_t)p * NF + k1 * 4096;
    const float2* __restrict__ wf = g_filt + k1 * 4096;
    float2 v[16];
    // forward stage 1: fft16 over a (stride 256), coalesced load
    #pragma unroll
    for (int a = 0; a < 16; a++) v[a] = base[a * 256 + t];
    fft16<-1>(v);  // -> v[t1] = F[t1][s=t]
    // T1 twiddle e^{-2pi i t * t1 / 4096}
    { float s_, c_; __sincosf(-TWO_PI * (float)t / 4096.0f, &s_, &c_);
      float2 w = make_float2(c_, s_), tw = make_float2(1.f, 0.f);
      #pragma unroll
      for (int t1 = 0; t1 < 16; t1++) { v[t1] = cmul(v[t1], tw); tw = cmul(tw, w); } }
    // transpose
    #pragma unroll
    for (int t1 = 0; t1 < 16; t1++) sh[t1 * 257 + t] = v[t1];
    __syncthreads();
    #pragma unroll
    for (int j = 0; j < 16; j++) v[j] = sh[g * 257 + 16 * j + l];
    // forward stage 2+3: 256-pt FFT over s for row t1=g
    fft256_core<-1>(v, l, g, sh);
    // pointwise multiply (register-coalesced; wf layout matches exactly)
    #pragma unroll
    for (int u2 = 0; u2 < 16; u2++)
        v[u2] = cmul(v[u2], wf[u2 * 256 + t]);
    // inverse stage 3+2: 256-pt inverse over u
    fft256_core<1>(v, l, g, sh);
    // undo T1: e^{+2pi i s*g/4096}, s = 16*sigma + l
    { float s_, c_; __sincosf(TWO_PI * (float)(l * g) / 4096.0f, &s_, &c_);
      float ss, cs; __sincosf(TWO_PI * (float)g / 256.0f, &ss, &cs);
      float2 tw = make_float2(c_, s_), w = make_float2(cs, ss);
      #pragma unroll
      for (int sg = 0; sg < 16; sg++) { v[sg] = cmul(v[sg], tw); tw = cmul(tw, w); } }
    // transpose back: thread t gets all t1 for s=t
    __syncthreads();
    #pragma unroll
    for (int sg = 0; sg < 16; sg++) sh[g * 257 + 16 * sg + l] = v[sg];
    __syncthreads();
    #pragma unroll
    for (int t1 = 0; t1 < 16; t1++) v[t1] = sh[t1 * 257 + t];
    // inverse stage 1: fft16 over t1 -> v[a] = z'[256a + t]
    fft16<1>(v);
    // conj inter-stage twiddle e^{+2pi i n2 k1 / 65536}, n2 = 256a + t
    { float s_, c_; __sincosf(TWO_PI * (float)(t * k1) / 65536.0f, &s_, &c_);
      float ss, cs; __sincosf(TWO_PI * (float)k1 / 256.0f, &ss, &cs);
      float2 tw = make_float2(c_, s_), w = make_float2(cs, ss);
      #pragma unroll
      for (int a = 0; a < 16; a++) {
          base[a * 256 + t] = cmul(v[a], tw);
          tw = cmul(tw, w);
      } }
}

// ======== K3: inverse stage A (16-pt over k1) + scale + write y — no smem ========
__global__ void __launch_bounds__(256) k_colA_inv(float* __restrict__ y) {
    int t = threadIdx.x;
    int p = blockIdx.x >> 4, blk = blockIdx.x & 15;
    int n2 = blk * 256 + t;
    const float2* src = g_work + (size_t)p * NF;
    float2 v[16];
    #pragma unroll
    for (int k1 = 0; k1 < 16; k1++)
        v[k1] = src[k1 * 4096 + n2];
    fft16<1>(v);  // over k1 -> v[n1]
    const float inv = 1.0f / 65536.0f;
    float* yr = y + (size_t)(2 * p) * TLEN;
    float* yi = y + (size_t)(2 * p + 1) * TLEN;
    #pragma unroll
    for (int n1 = 0; n1 < 8; n1++) {  // only n < T
        int n = n1 * 4096 + n2;
        yr[n] = v[n1].x * inv;
        yi[n] = v[n1].y * inv;
    }
}

extern "C" void kernel_launch(void* const* d_in, const int* in_sizes, int n_in,
                              void* d_out, int out_size) {
    const float* x = (const float*)d_in[0];
    const float* f = (const float*)d_in[1];
    float* y = (float*)d_out;

    k_filt_colA<<<16, 256>>>(f);    // filter: stage A + twiddle
    k_filt_rowB<<<16, 256>>>();     // filter: 4096-pt row fwd -> K2 layout
    k_colA<<<2048, 256>>>(x);       // signals: stage A (pure registers)
    k_rowB<<<2048, 256>>>();        // 4096 fwd, *Wf, 4096 inv, conj twiddle
    k_colA_inv<<<2048, 256>>>(y);   // stage A inverse + scale (pure registers)
}

// round 7
// speedup vs baseline: 1.3542x; 1.0005x over previous
#include <cuda_runtime.h>
#include <math.h>

#define TLEN 32768
#define NF   65536
#define TWO_PI 6.283185307179586476925f

// 128 complex signals x 65536 points = 64 MB scratch.
// Layout between kernels: g_work[p][k1*4096 + n2]  (k1 = 0..15, n2 = 0..4095)
__device__ float2 g_work[128 * 65536];
// filter spectrum; after k_filt_rowB stored K2-register-matched:
// g_filt[k1*4096 + u2*256 + t]
__device__ float2 g_filt[65536];

__device__ __forceinline__ float2 cmul(float2 a, float2 b) {
    return make_float2(fmaf(a.x, b.x, -(a.y * b.y)), fmaf(a.x, b.y, a.y * b.x));
}

// packed f32x2 add/sub (Blackwell): 1 instruction for a complex add/sub
__device__ __forceinline__ float2 f2add(float2 a, float2 b) {
    float2 c;
    asm("{\n\t.reg .b64 ra, rb, rc;\n\t"
        "mov.b64 ra, {%2, %3};\n\t"
        "mov.b64 rb, {%4, %5};\n\t"
        "add.rn.f32x2 rc, ra, rb;\n\t"
        "mov.b64 {%0, %1}, rc;\n\t}"
        : "=f"(c.x), "=f"(c.y)
        : "f"(a.x), "f"(a.y), "f"(b.x), "f"(b.y));
    return c;
}
__device__ __forceinline__ float2 f2sub(float2 a, float2 b) {
    float2 c;
    asm("{\n\t.reg .b64 ra, rb, rc;\n\t"
        "mov.b64 ra, {%2, %3};\n\t"
        "mov.b64 rb, {%4, %5};\n\t"
        "sub.rn.f32x2 rc, ra, rb;\n\t"
        "mov.b64 {%0, %1}, rc;\n\t}"
        : "=f"(c.x), "=f"(c.y)
        : "f"(a.x), "f"(a.y), "f"(b.x), "f"(b.y));
    return c;
}

template<int SIGN>
__device__ __forceinline__ void fft4(float2& a0, float2& a1, float2& a2, float2& a3) {
    float2 s0 = f2add(a0, a2);
    float2 d0 = f2sub(a0, a2);
    float2 s1 = f2add(a1, a3);
    float2 d1 = f2sub(a1, a3);
    float2 wd1 = (SIGN < 0) ? make_float2(d1.y, -d1.x) : make_float2(-d1.y, d1.x);
    a0 = f2add(s0, s1);
    a2 = f2sub(s0, s1);
    a1 = f2add(d0, wd1);
    a3 = f2sub(d0, wd1);
}

template<int SIGN>
__device__ __forceinline__ float2 w16f(int m) {
    const float C[10] = {1.f, 0.92387953251128675613f, 0.70710678118654752440f,
                         0.38268343236508977173f, 0.f, -0.38268343236508977173f,
                         -0.70710678118654752440f, -0.92387953251128675613f,
                         -1.f, -0.92387953251128675613f};
    const float S[10] = {0.f, 0.38268343236508977173f, 0.70710678118654752440f,
                         0.92387953251128675613f, 1.f, 0.92387953251128675613f,
                         0.70710678118654752440f, 0.38268343236508977173f,
                         0.f, -0.38268343236508977173f};
    return make_float2(C[m], (SIGN < 0) ? -S[m] : S[m]);
}

// 16-point DFT, natural-order in/out: X[k] = sum_n v[n] e^{SIGN*2pi i nk/16}
template<int SIGN>
__device__ __forceinline__ void fft16(float2 v[16]) {
    #pragma unroll
    for (int b = 0; b < 4; b++) fft4<SIGN>(v[b], v[4 + b], v[8 + b], v[12 + b]);
    #pragma unroll
    for (int p = 1; p < 4; p++) {
        #pragma unroll
        for (int b = 1; b < 4; b++)
            v[4 * p + b] = cmul(v[4 * p + b], w16f<SIGN>(b * p));
    }
    #pragma unroll
    for (int p = 0; p < 4; p++) fft4<SIGN>(v[4 * p + 0], v[4 * p + 1], v[4 * p + 2], v[4 * p + 3]);
    float2 o[16];
    #pragma unroll
    for (int q = 0; q < 4; q++)
        #pragma unroll
        for (int p = 0; p < 4; p++) o[4 * q + p] = v[4 * p + q];
    #pragma unroll
    for (int i = 0; i < 16; i++) v[i] = o[i];
}

// v[k] *= t0 * w^k for k = 0..15, via 4 independent chains of 4 (dep depth ~6
// instead of 16 for the naive serial recurrence).
__device__ __forceinline__ void twmul16(float2 v[16], float2 t0, float2 w) {
    float2 t2 = cmul(w, w);
    float2 t4 = cmul(t2, t2);
    float2 t8 = cmul(t4, t4);
    float2 a = t0;
    float2 b = cmul(t0, t4);
    float2 c = cmul(t0, t8);
    float2 d = cmul(b, t8);
    #pragma unroll
    for (int i = 0; i < 4; i++) {
        v[i]      = cmul(v[i], a);
        v[4 + i]  = cmul(v[4 + i], b);
        v[8 + i]  = cmul(v[8 + i], c);
        v[12 + i] = cmul(v[12 + i], d);
        if (i < 3) { a = cmul(a, w); b = cmul(b, w); c = cmul(c, w); d = cmul(d, w); }
    }
}
__device__ const float2 C_ONE = {1.f, 0.f};

// 256-point DFT across 16 lanes (lane l holds v[j]=s[16j+l] on entry;
// on exit lane l holds v[k2]=X[16*k2+l]). Exchange via shared row g.
template<int SIGN>
__device__ __forceinline__ void fft256_core(float2 v[16], int l, int g,
                                            float2* sh) {
    fft16<SIGN>(v);
    float sv, cv;
    __sincosf(((SIGN < 0) ? -TWO_PI : TWO_PI) * (float)l / 256.0f, &sv, &cv);
    twmul16(v, make_float2(1.f, 0.f), make_float2(cv, sv));
    __syncthreads();
    #pragma unroll
    for (int k1 = 0; k1 < 16; k1++)
        sh[g * 257 + k1 * 16 + l] = v[k1];
    __syncthreads();
    #pragma unroll
    for (int n2 = 0; n2 < 16; n2++)
        v[n2] = sh[g * 257 + l * 16 + n2];
    fft16<SIGN>(v);
}

// ======== K1: stage A (16-pt column FFT over n1, stride 4096) — no smem ========
__global__ void __launch_bounds__(256) k_colA(const float* __restrict__ x) {
    int t = threadIdx.x;
    int p = blockIdx.x >> 4, blk = blockIdx.x & 15;
    int n2 = blk * 256 + t;
    const float* xr = x + (size_t)(2 * p) * TLEN;
    const float* xi = x + (size_t)(2 * p + 1) * TLEN;
    float2 v[16];
    #pragma unroll
    for (int n1 = 0; n1 < 16; n1++) {
        if (n1 < 8) {  // n >= 32768 is zero padding
            int n = n1 * 4096 + n2;
            v[n1] = make_float2(xr[n], xi[n]);
        } else v[n1] = make_float2(0.f, 0.f);
    }
    fft16<-1>(v);  // over n1 -> v[k1]
    // twiddle e^{-2pi i n2 k1 / 65536}
    float s, c; __sincosf(-TWO_PI * (float)n2 / 65536.0f, &s, &c);
    twmul16(v, make_float2(1.f, 0.f), make_float2(c, s));
    float2* dst = g_work + (size_t)p * NF;
    #pragma unroll
    for (int k1 = 0; k1 < 16; k1++)
        dst[k1 * 4096 + n2] = v[k1];
}

// ======== K0a: filter stage A (same as K1, real input, natural layout) ========
__global__ void __launch_bounds__(256) k_filt_colA(const float* __restrict__ f) {
    int t = threadIdx.x;
    int n2 = blockIdx.x * 256 + t;
    float2 v[16];
    #pragma unroll
    for (int n1 = 0; n1 < 16; n1++) {
        if (n1 < 8) v[n1] = make_float2(f[n1 * 4096 + n2], 0.f);
        else v[n1] = make_float2(0.f, 0.f);
    }
    fft16<-1>(v);
    float s, c; __sincosf(-TWO_PI * (float)n2 / 65536.0f, &s, &c);
    twmul16(v, make_float2(1.f, 0.f), make_float2(c, s));
    #pragma unroll
    for (int k1 = 0; k1 < 16; k1++)
        g_filt[k1 * 4096 + n2] = v[k1];
}

// ======== K0b: filter row-forward (4096-pt), writes K2-register-matched ========
__global__ void __launch_bounds__(256) k_filt_rowB() {
    __shared__ float2 sh[16 * 257];
    int t = threadIdx.x;
    int l = t >> 4, g = t & 15;
    int k1 = blockIdx.x;
    float2* base = g_filt + k1 * 4096;
    float2 v[16];
    #pragma unroll
    for (int a = 0; a < 16; a++) v[a] = base[a * 256 + t];
    fft16<-1>(v);  // over a -> v[t1] = F[t1][s=t]
    // T1 twiddle e^{-2pi i t * t1 / 4096}
    { float s_, c_; __sincosf(-TWO_PI * (float)t / 4096.0f, &s_, &c_);
      twmul16(v, make_float2(1.f, 0.f), make_float2(c_, s_)); }
    // transpose: thread (l,g) gets row t1=g, elements s=16j+l
    #pragma unroll
    for (int t1 = 0; t1 < 16; t1++) sh[t1 * 257 + t] = v[t1];
    __syncthreads();
    #pragma unroll
    for (int j = 0; j < 16; j++) v[j] = sh[g * 257 + 16 * j + l];
    fft256_core<-1>(v, l, g, sh);
    // v[u2] = Wf[k1-row][u = 16u2+l] for t1=g; store K2-matched layout
    #pragma unroll
    for (int u2 = 0; u2 < 16; u2++) base[u2 * 256 + t] = v[u2];
}

// ======== K2: per-row 4096-pt FFT -> *Wf -> inverse (conj twiddle moved to K3) ==
__global__ void __launch_bounds__(256, 4) k_rowB() {
    __shared__ float2 sh[16 * 257];
    int t = threadIdx.x;
    int l = t >> 4, g = t & 15;
    int p = blockIdx.x >> 4, k1 = blockIdx.x & 15;
    float2* base = g_work + (size_t)p * NF + k1 * 4096;
    const float2* __restrict__ wf = g_filt + k1 * 4096;
    float2 v[16];
    // forward stage 1: fft16 over a (stride 256), coalesced load
    #pragma unroll
    for (int a = 0; a < 16; a++) v[a] = base[a * 256 + t];
    fft16<-1>(v);  // -> v[t1] = F[t1][s=t]
    // T1 twiddle e^{-2pi i t * t1 / 4096}
    { float s_, c_; __sincosf(-TWO_PI * (float)t / 4096.0f, &s_, &c_);
      twmul16(v, make_float2(1.f, 0.f), make_float2(c_, s_)); }
    // transpose
    #pragma unroll
    for (int t1 = 0; t1 < 16; t1++) sh[t1 * 257 + t] = v[t1];
    __syncthreads();
    #pragma unroll
    for (int j = 0; j < 16; j++) v[j] = sh[g * 257 + 16 * j + l];
    // forward stage 2+3: 256-pt FFT over s for row t1=g
    fft256_core<-1>(v, l, g, sh);
    // pointwise multiply (register-coalesced; wf layout matches exactly)
    #pragma unroll
    for (int u2 = 0; u2 < 16; u2++)
        v[u2] = cmul(v[u2], wf[u2 * 256 + t]);
    // inverse stage 3+2: 256-pt inverse over u
    fft256_core<1>(v, l, g, sh);
    // undo T1: e^{+2pi i s*g/4096}, s = 16*sigma + l
    { float s_, c_; __sincosf(TWO_PI * (float)(l * g) / 4096.0f, &s_, &c_);
      float ss, cs; __sincosf(TWO_PI * (float)g / 256.0f, &ss, &cs);
      twmul16(v, make_float2(c_, s_), make_float2(cs, ss)); }
    // transpose back: thread t gets all t1 for s=t
    __syncthreads();
    #pragma unroll
    for (int sg = 0; sg < 16; sg++) sh[g * 257 + 16 * sg + l] = v[sg];
    __syncthreads();
    #pragma unroll
    for (int t1 = 0; t1 < 16; t1++) v[t1] = sh[t1 * 257 + t];
    // inverse stage 1: fft16 over t1 -> v[a] = z'[256a + t]; store directly
    fft16<1>(v);
    #pragma unroll
    for (int a = 0; a < 16; a++)
        base[a * 256 + t] = v[a];
}

// ======== K3: conj twiddle + inverse stage A (16-pt over k1) + scale + y ========
__global__ void __launch_bounds__(256) k_colA_inv(float* __restrict__ y) {
    int t = threadIdx.x;
    int p = blockIdx.x >> 4, blk = blockIdx.x & 15;
    int n2 = blk * 256 + t;
    const float2* src = g_work + (size_t)p * NF;
    float2 v[16];
    #pragma unroll
    for (int k1 = 0; k1 < 16; k1++)
        v[k1] = src[k1 * 4096 + n2];
    // conj inter-stage twiddle e^{+2pi i n2 k1 / 65536} (moved from K2)
    { float s, c; __sincosf(TWO_PI * (float)n2 / 65536.0f, &s, &c);
      twmul16(v, make_float2(1.f, 0.f), make_float2(c, s)); }
    fft16<1>(v);  // over k1 -> v[n1]
    const float inv = 1.0f / 65536.0f;
    float* yr = y + (size_t)(2 * p) * TLEN;
    float* yi = y + (size_t)(2 * p + 1) * TLEN;
    #pragma unroll
    for (int n1 = 0; n1 < 8; n1++) {  // only n < T
        int n = n1 * 4096 + n2;
        yr[n] = v[n1].x * inv;
        yi[n] = v[n1].y * inv;
    }
}

extern "C" void kernel_launch(void* const* d_in, const int* in_sizes, int n_in,
                              void* d_out, int out_size) {
    const float* x = (const float*)d_in[0];
    const float* f = (const float*)d_in[1];
    float* y = (float*)d_out;

    k_filt_colA<<<16, 256>>>(f);    // filter: stage A + twiddle
    k_filt_rowB<<<16, 256>>>();     // filter: 4096-pt row fwd -> K2 layout
    k_colA<<<2048, 256>>>(x);       // signals: stage A (pure registers)
    k_rowB<<<2048, 256>>>();        // 4096 fwd, *Wf, 4096 inv
    k_colA_inv<<<2048, 256>>>(y);   // conj twiddle + stage A inverse + scale
}